// round 15
// baseline (speedup 1.0000x reference)
#include <cuda_runtime.h>

// FSNeuronDecoupled: T=8 spiking-threshold scan over x[8,2097152,1] fp32.
//   per element: v=x; for t: s=(v>th_t); v-=h_t*s; y+=d_t*s
//   th_t=theta[g]^-(t+1), h_t=h[g]^-(t+1), d_t=d[g]^-(t+1), g=t<4?0:1.
//
// FAST PATH (runtime-guarded, uniform): theta==h==d==2.0 for both grains
// makes the scan an exact 8-bit greedy binary expansion:
//   y = clamp(ceil(x*256)*2^-8 - 2^-8, 0, 255/256)    (bit-exact)
//
// R15: 256-bit vector ld/st (sm_100a ld/st.global.v8.f32) — same bytes
// per thread-iteration as the 18.6us terminal config (32 B), but one
// request instead of two: halves LSU instructions and L1tex wavefront
// entries per byte. Last untested axis (request shape). Pipeline,
// residency (8 blk/SM x 148), and math unchanged.

#define THREADS 256
// float8 = 32 bytes per thread per tile; TILE8 in float8 units
#define TILE8   THREADS              // 256 float8 = 8192 bytes per tile

struct f8 { float v[8]; };

__device__ __forceinline__ void ldg_v8(f8& r, const float* p) {
    asm volatile(
        "ld.global.v8.f32 {%0,%1,%2,%3,%4,%5,%6,%7}, [%8];"
        : "=f"(r.v[0]), "=f"(r.v[1]), "=f"(r.v[2]), "=f"(r.v[3]),
          "=f"(r.v[4]), "=f"(r.v[5]), "=f"(r.v[6]), "=f"(r.v[7])
        : "l"(p));
}

__device__ __forceinline__ void stg_v8(float* p, const f8& r) {
    asm volatile(
        "st.global.v8.f32 [%0], {%1,%2,%3,%4,%5,%6,%7,%8};"
        :: "l"(p),
           "f"(r.v[0]), "f"(r.v[1]), "f"(r.v[2]), "f"(r.v[3]),
           "f"(r.v[4]), "f"(r.v[5]), "f"(r.v[6]), "f"(r.v[7])
        : "memory");
}

__global__ __launch_bounds__(THREADS, 8)
void fsneuron_kernel(const float* __restrict__ x,
                     float* __restrict__ y,
                     const float* __restrict__ dp_,
                     const float* __restrict__ hp_,
                     const float* __restrict__ thp_,
                     int n) {
    const float th0 = __ldg(&thp_[0]), th1 = __ldg(&thp_[1]);
    const float h0  = __ldg(&hp_[0]),  h1  = __ldg(&hp_[1]);
    const float d0  = __ldg(&dp_[0]),  d1  = __ldg(&dp_[1]);

    const int stride = gridDim.x;
    const bool magic = (th0 == 2.0f) & (th1 == 2.0f) &
                       (h0  == 2.0f) & (h1  == 2.0f) &
                       (d0  == 2.0f) & (d1  == 2.0f);
    const bool exact = (n % (TILE8 * 8)) == 0;   // bench: n = 16,777,216 ✓

    if (magic & exact) {
        const int n8 = n >> 3;                    // float8 count
        const int ntiles = n8 / TILE8;            // 8192
        int tile = blockIdx.x;
        f8 cur;
        if (tile < ntiles)
            ldg_v8(cur, x + (size_t)(tile * TILE8 + threadIdx.x) * 8);

        for (; tile < ntiles; tile += stride) {
            // prefetch next tile FIRST — load stays in flight during
            // compute + store of the current tile
            const int nt = tile + stride;
            f8 nxt;
            if (nt < ntiles)
                ldg_v8(nxt, x + (size_t)(nt * TILE8 + threadIdx.x) * 8);

            // y = clamp(ceil(x*256)*2^-8 - 2^-8, 0, 255/256)
#pragma unroll
            for (int j = 0; j < 8; j++) {
                float c_ = ceilf(cur.v[j] * 256.0f);
                float t_ = fmaf(c_, 0.00390625f, -0.00390625f);
                cur.v[j] = fminf(fmaxf(t_, 0.0f), 0.99609375f);
            }

            stg_v8(y + (size_t)(tile * TILE8 + threadIdx.x) * 8, cur);
            cur = nxt;
        }
        return;
    }

    // ---- general fallback: explicit 8-step scan, float4 path with
    //      bounds checks (correct for any inputs; never runs on bench) ----
    const float rth0 = __frcp_rn(th0), rth1 = __frcp_rn(th1);
    const float rh0  = __frcp_rn(h0),  rh1  = __frcp_rn(h1);
    const float rd0  = __frcp_rn(d0),  rd1  = __frcp_rn(d1);

    const int n4 = n >> 2;
    const int TILE4 = THREADS * 2;
    const int ntiles4 = (n4 + TILE4 - 1) / TILE4;
    const float4* x4 = (const float4*)x;
    float4* y4 = (float4*)y;

    for (int tile = blockIdx.x; tile < ntiles4; tile += stride) {
        const int base = tile * TILE4 + threadIdx.x;
        float4 v[2], a[2];
#pragma unroll
        for (int k = 0; k < 2; k++) {
            int i = base + k * THREADS;
            v[k] = (i < n4) ? x4[i] : make_float4(0.f, 0.f, 0.f, 0.f);
            a[k] = make_float4(0.f, 0.f, 0.f, 0.f);
        }

        if (magic) {
#pragma unroll
            for (int k = 0; k < 2; k++) {
                #define Q(f) {                                        \
                    float c_ = ceilf((f) * 256.0f);                   \
                    float t_ = fmaf(c_, 0.00390625f, -0.00390625f);   \
                    (f) = fminf(fmaxf(t_, 0.0f), 0.99609375f);        \
                }
                Q(v[k].x); Q(v[k].y); Q(v[k].z); Q(v[k].w);
                #undef Q
                a[k] = v[k];
            }
        } else {
#define LANE(vv, aa) { if (vv > thp) { vv -= hp; aa += dpw; } }
#define STEP()                                    \
            {                                     \
                _Pragma("unroll")                 \
                for (int k = 0; k < 2; k++) {     \
                    LANE(v[k].x, a[k].x);         \
                    LANE(v[k].y, a[k].y);         \
                    LANE(v[k].z, a[k].z);         \
                    LANE(v[k].w, a[k].w);         \
                }                                 \
            }
            float thp = rth0, hp = rh0, dpw = rd0;
#pragma unroll
            for (int t = 0; t < 4; t++) {
                STEP();
                thp *= rth0; hp *= rh0; dpw *= rd0;
            }
            {
                float r2 = rth1 * rth1; thp = r2 * r2 * rth1;
                float s2 = rh1  * rh1;  hp  = s2 * s2 * rh1;
                float u2 = rd1  * rd1;  dpw = u2 * u2 * rd1;
            }
#pragma unroll
            for (int t = 4; t < 8; t++) {
                STEP();
                thp *= rth1; hp *= rh1; dpw *= rd1;
            }
#undef STEP
#undef LANE
        }

#pragma unroll
        for (int k = 0; k < 2; k++) {
            int i = base + k * THREADS;
            if (i < n4) y4[i] = a[k];
        }
    }
}

extern "C" void kernel_launch(void* const* d_in, const int* in_sizes, int n_in,
                              void* d_out, int out_size) {
    const float* x     = (const float*)d_in[0];  // 16,777,216 fp32
    const float* d     = (const float*)d_in[1];  // 2
    const float* h     = (const float*)d_in[2];  // 2
    const float* theta = (const float*)d_in[3];  // 2
    float* y = (float*)d_out;

    int n = in_sizes[0];

    // Persistent grid: 148 SMs x 8 resident blocks.
    int blocks = 148 * 8;            // 1184
    int ntiles = (n / 8 + TILE8 - 1) / TILE8;   // 8192 on bench
    if (blocks > ntiles) blocks = ntiles;

    fsneuron_kernel<<<blocks, THREADS>>>(x, y, d, h, theta, n);
}

// round 16
// speedup vs baseline: 1.0096x; 1.0096x over previous
#include <cuda_runtime.h>

// FSNeuronDecoupled: T=8 spiking-threshold scan over x[8,2097152,1] fp32.
//   per element: v=x; for t: s=(v>th_t); v-=h_t*s; y+=d_t*s
//   th_t=theta[g]^-(t+1), h_t=h[g]^-(t+1), d_t=d[g]^-(t+1), g=t<4?0:1.
//
// FAST PATH (runtime-guarded, uniform): theta==h==d==2.0 for both grains
// makes the scan an exact 8-bit greedy binary expansion:
//   y = clamp(ceil(x*256)*2^-8 - 2^-8, 0, 255/256)    (bit-exact)
//
// TERMINAL KERNEL — confirmed best across the session (18.56/18.62/18.69us
// in three independent runs; ~7.1 TB/s aggregate R+W = ~89% of spec HBM
// for a 1:1 compulsory read/write stream). Bracketed and rejected:
// deeper pipelines, v8 256-bit requests, streaming cache ops, predicate
// elimination, occupancy trades, block-shape changes — all neutral or
// negative. Bottleneck is DRAM R/W turnaround on compulsory traffic.
// Config: UNROLL=2 software-pipelined double buffer, 32 regs,
// 8 blocks/SM x 148 SMs persistent, default cache policy.

#define THREADS 256
#define UNROLL  2
#define TILE    (THREADS * UNROLL)   // 512 float4 per tile

__global__ __launch_bounds__(THREADS, 8)
void fsneuron_kernel(const float4* __restrict__ x,
                     float4* __restrict__ y,
                     const float* __restrict__ dp_,
                     const float* __restrict__ hp_,
                     const float* __restrict__ thp_,
                     int n4) {
    const float th0 = __ldg(&thp_[0]), th1 = __ldg(&thp_[1]);
    const float h0  = __ldg(&hp_[0]),  h1  = __ldg(&hp_[1]);
    const float d0  = __ldg(&dp_[0]),  d1  = __ldg(&dp_[1]);

    const int ntiles = (n4 + TILE - 1) / TILE;
    const int stride = gridDim.x;
    const bool magic = (th0 == 2.0f) & (th1 == 2.0f) &
                       (h0  == 2.0f) & (h1  == 2.0f) &
                       (d0  == 2.0f) & (d1  == 2.0f);

    if (magic) {
        int tile = blockIdx.x;
        float4 cur[UNROLL];
        if (tile < ntiles) {
            const int base = tile * TILE + threadIdx.x;
#pragma unroll
            for (int k = 0; k < UNROLL; k++) {
                int i = base + k * THREADS;
                cur[k] = (i < n4) ? x[i] : make_float4(0.f, 0.f, 0.f, 0.f);
            }
        }
        for (; tile < ntiles; tile += stride) {
            // prefetch next tile FIRST — keeps loads in flight during
            // compute + store of the current tile
            const int nt = tile + stride;
            float4 nxt[UNROLL];
            if (nt < ntiles) {
                const int nb = nt * TILE + threadIdx.x;
#pragma unroll
                for (int k = 0; k < UNROLL; k++) {
                    int i = nb + k * THREADS;
                    nxt[k] = (i < n4) ? x[i]
                                      : make_float4(0.f, 0.f, 0.f, 0.f);
                }
            }

            // y = clamp(ceil(x*256)*2^-8 - 2^-8, 0, 255/256)
#pragma unroll
            for (int k = 0; k < UNROLL; k++) {
                #define Q(f) {                                        \
                    float c_ = ceilf((f) * 256.0f);                   \
                    float t_ = fmaf(c_, 0.00390625f, -0.00390625f);   \
                    (f) = fminf(fmaxf(t_, 0.0f), 0.99609375f);        \
                }
                Q(cur[k].x); Q(cur[k].y); Q(cur[k].z); Q(cur[k].w);
                #undef Q
            }

            const int base = tile * TILE + threadIdx.x;
#pragma unroll
            for (int k = 0; k < UNROLL; k++) {
                int i = base + k * THREADS;
                if (i < n4) y[i] = cur[k];   // default write-back
            }
#pragma unroll
            for (int k = 0; k < UNROLL; k++)
                cur[k] = nxt[k];
        }
        return;
    }

    // ---- general fallback: explicit 8-step scan (correct for any inputs;
    //      never executes on bench data) ----
    const float rth0 = __frcp_rn(th0), rth1 = __frcp_rn(th1);
    const float rh0  = __frcp_rn(h0),  rh1  = __frcp_rn(h1);
    const float rd0  = __frcp_rn(d0),  rd1  = __frcp_rn(d1);

    for (int tile = blockIdx.x; tile < ntiles; tile += stride) {
        const int base = tile * TILE + threadIdx.x;
        float4 v[UNROLL], a[UNROLL];
#pragma unroll
        for (int k = 0; k < UNROLL; k++) {
            int i = base + k * THREADS;
            v[k] = (i < n4) ? x[i] : make_float4(0.f, 0.f, 0.f, 0.f);
            a[k] = make_float4(0.f, 0.f, 0.f, 0.f);
        }

#define LANE(vv, aa) { if (vv > thp) { vv -= hp; aa += dpw; } }
#define STEP()                                    \
        {                                         \
            _Pragma("unroll")                     \
            for (int k = 0; k < UNROLL; k++) {    \
                LANE(v[k].x, a[k].x);             \
                LANE(v[k].y, a[k].y);             \
                LANE(v[k].z, a[k].z);             \
                LANE(v[k].w, a[k].w);             \
            }                                     \
        }
        float thp = rth0, hp = rh0, dpw = rd0;
#pragma unroll
        for (int t = 0; t < 4; t++) {
            STEP();
            thp *= rth0; hp *= rh0; dpw *= rd0;
        }
        {
            float r2 = rth1 * rth1; thp = r2 * r2 * rth1;
            float s2 = rh1  * rh1;  hp  = s2 * s2 * rh1;
            float u2 = rd1  * rd1;  dpw = u2 * u2 * rd1;
        }
#pragma unroll
        for (int t = 4; t < 8; t++) {
            STEP();
            thp *= rth1; hp *= rh1; dpw *= rd1;
        }
#undef STEP
#undef LANE

#pragma unroll
        for (int k = 0; k < UNROLL; k++) {
            int i = base + k * THREADS;
            if (i < n4) y[i] = a[k];
        }
    }
}

extern "C" void kernel_launch(void* const* d_in, const int* in_sizes, int n_in,
                              void* d_out, int out_size) {
    const float* x     = (const float*)d_in[0];  // 16,777,216 fp32
    const float* d     = (const float*)d_in[1];  // 2
    const float* h     = (const float*)d_in[2];  // 2
    const float* theta = (const float*)d_in[3];  // 2
    float* y = (float*)d_out;

    int n  = in_sizes[0];
    int n4 = n >> 2;                 // 4,194,304 float4 (exact)

    // Persistent grid: 148 SMs x 8 resident blocks.
    int blocks = 148 * 8;            // 1184 -> ~7 tiles per block
    int ntiles = (n4 + TILE - 1) / TILE;
    if (blocks > ntiles) blocks = ntiles;

    fsneuron_kernel<<<blocks, THREADS>>>((const float4*)x, (float4*)y,
                                         d, h, theta, n4);
}

// round 17
// speedup vs baseline: 1.0223x; 1.0125x over previous
#include <cuda_runtime.h>

// FSNeuronDecoupled: T=8 spiking-threshold scan over x[8,2097152,1] fp32.
//   per element: v=x; for t: s=(v>th_t); v-=h_t*s; y+=d_t*s
//   th_t=theta[g]^-(t+1), h_t=h[g]^-(t+1), d_t=d[g]^-(t+1), g=t<4?0:1.
//
// FAST PATH (runtime-guarded, uniform): theta==h==d==2.0 for both grains
// makes the scan an exact 8-bit greedy binary expansion:
//   y = clamp(ceil(x*256)*2^-8 - 2^-8, 0, 255/256)    (bit-exact)
//
// FINAL KERNEL — confirmed optimum over a 16-round search
// (18.56/18.62/18.69/18.85us across four independent runs; ~7.2 TB/s
// aggregate R+W = ~90% of spec HBM on a 1:1 compulsory read/write
// stream; ideal floor 16.8us). Bracketed and rejected: deeper
// pipelines, v8 256-bit requests, streaming cache ops, predicate
// elimination, occupancy trades, block-shape changes — all neutral or
// negative. Residual gap is DRAM R/W bus turnaround; not
// kernel-addressable. Config: UNROLL=2 software-pipelined double
// buffer, 32 regs, 8 blocks/SM x 148 SMs persistent, default cache.

#define THREADS 256
#define UNROLL  2
#define TILE    (THREADS * UNROLL)   // 512 float4 per tile

__global__ __launch_bounds__(THREADS, 8)
void fsneuron_kernel(const float4* __restrict__ x,
                     float4* __restrict__ y,
                     const float* __restrict__ dp_,
                     const float* __restrict__ hp_,
                     const float* __restrict__ thp_,
                     int n4) {
    const float th0 = __ldg(&thp_[0]), th1 = __ldg(&thp_[1]);
    const float h0  = __ldg(&hp_[0]),  h1  = __ldg(&hp_[1]);
    const float d0  = __ldg(&dp_[0]),  d1  = __ldg(&dp_[1]);

    const int ntiles = (n4 + TILE - 1) / TILE;
    const int stride = gridDim.x;
    const bool magic = (th0 == 2.0f) & (th1 == 2.0f) &
                       (h0  == 2.0f) & (h1  == 2.0f) &
                       (d0  == 2.0f) & (d1  == 2.0f);

    if (magic) {
        int tile = blockIdx.x;
        float4 cur[UNROLL];
        if (tile < ntiles) {
            const int base = tile * TILE + threadIdx.x;
#pragma unroll
            for (int k = 0; k < UNROLL; k++) {
                int i = base + k * THREADS;
                cur[k] = (i < n4) ? x[i] : make_float4(0.f, 0.f, 0.f, 0.f);
            }
        }
        for (; tile < ntiles; tile += stride) {
            // prefetch next tile FIRST — keeps loads in flight during
            // compute + store of the current tile
            const int nt = tile + stride;
            float4 nxt[UNROLL];
            if (nt < ntiles) {
                const int nb = nt * TILE + threadIdx.x;
#pragma unroll
                for (int k = 0; k < UNROLL; k++) {
                    int i = nb + k * THREADS;
                    nxt[k] = (i < n4) ? x[i]
                                      : make_float4(0.f, 0.f, 0.f, 0.f);
                }
            }

            // y = clamp(ceil(x*256)*2^-8 - 2^-8, 0, 255/256)
#pragma unroll
            for (int k = 0; k < UNROLL; k++) {
                #define Q(f) {                                        \
                    float c_ = ceilf((f) * 256.0f);                   \
                    float t_ = fmaf(c_, 0.00390625f, -0.00390625f);   \
                    (f) = fminf(fmaxf(t_, 0.0f), 0.99609375f);        \
                }
                Q(cur[k].x); Q(cur[k].y); Q(cur[k].z); Q(cur[k].w);
                #undef Q
            }

            const int base = tile * TILE + threadIdx.x;
#pragma unroll
            for (int k = 0; k < UNROLL; k++) {
                int i = base + k * THREADS;
                if (i < n4) y[i] = cur[k];   // default write-back
            }
#pragma unroll
            for (int k = 0; k < UNROLL; k++)
                cur[k] = nxt[k];
        }
        return;
    }

    // ---- general fallback: explicit 8-step scan (correct for any inputs;
    //      never executes on bench data) ----
    const float rth0 = __frcp_rn(th0), rth1 = __frcp_rn(th1);
    const float rh0  = __frcp_rn(h0),  rh1  = __frcp_rn(h1);
    const float rd0  = __frcp_rn(d0),  rd1  = __frcp_rn(d1);

    for (int tile = blockIdx.x; tile < ntiles; tile += stride) {
        const int base = tile * TILE + threadIdx.x;
        float4 v[UNROLL], a[UNROLL];
#pragma unroll
        for (int k = 0; k < UNROLL; k++) {
            int i = base + k * THREADS;
            v[k] = (i < n4) ? x[i] : make_float4(0.f, 0.f, 0.f, 0.f);
            a[k] = make_float4(0.f, 0.f, 0.f, 0.f);
        }

#define LANE(vv, aa) { if (vv > thp) { vv -= hp; aa += dpw; } }
#define STEP()                                    \
        {                                         \
            _Pragma("unroll")                     \
            for (int k = 0; k < UNROLL; k++) {    \
                LANE(v[k].x, a[k].x);             \
                LANE(v[k].y, a[k].y);             \
                LANE(v[k].z, a[k].z);             \
                LANE(v[k].w, a[k].w);             \
            }                                     \
        }
        float thp = rth0, hp = rh0, dpw = rd0;
#pragma unroll
        for (int t = 0; t < 4; t++) {
            STEP();
            thp *= rth0; hp *= rh0; dpw *= rd0;
        }
        {
            float r2 = rth1 * rth1; thp = r2 * r2 * rth1;
            float s2 = rh1  * rh1;  hp  = s2 * s2 * rh1;
            float u2 = rd1  * rd1;  dpw = u2 * u2 * rd1;
        }
#pragma unroll
        for (int t = 4; t < 8; t++) {
            STEP();
            thp *= rth1; hp *= rh1; dpw *= rd1;
        }
#undef STEP
#undef LANE

#pragma unroll
        for (int k = 0; k < UNROLL; k++) {
            int i = base + k * THREADS;
            if (i < n4) y[i] = a[k];
        }
    }
}

extern "C" void kernel_launch(void* const* d_in, const int* in_sizes, int n_in,
                              void* d_out, int out_size) {
    const float* x     = (const float*)d_in[0];  // 16,777,216 fp32
    const float* d     = (const float*)d_in[1];  // 2
    const float* h     = (const float*)d_in[2];  // 2
    const float* theta = (const float*)d_in[3];  // 2
    float* y = (float*)d_out;

    int n  = in_sizes[0];
    int n4 = n >> 2;                 // 4,194,304 float4 (exact)

    // Persistent grid: 148 SMs x 8 resident blocks.
    int blocks = 148 * 8;            // 1184 -> ~7 tiles per block
    int ntiles = (n4 + TILE - 1) / TILE;
    if (blocks > ntiles) blocks = ntiles;

    fsneuron_kernel<<<blocks, THREADS>>>((const float4*)x, (float4*)y,
                                         d, h, theta, n4);
}